// round 14
// baseline (speedup 1.0000x reference)
#include <cuda_runtime.h>
#include <cuda_fp16.h>
#include <math.h>
#include <cstdint>

#define B 64
#define S 197
#define D 768
#define H 12
#define HD 64
#define M_TOT (B * S)          // 12608
#define NUM_REL 732
#define VT_PITCH 256
#define BP 198
#define LOG2E 1.44269504f

#define MBLK_A 50
#define MBLK_B 49
#define ROWS_A 6400

// -------- device scratch --------
__device__ __half g_xh[(size_t)M_TOT * D];
__device__ __half g_wh[(size_t)3 * D * D];
__device__ __half g_qh[(size_t)B * H * S * HD];
__device__ __half g_kh[(size_t)B * H * S * HD];
__device__ __half g_vt[(size_t)B * H * HD * VT_PITCH];
__device__ __half g_bias[(size_t)H * S * BP];

__device__ __forceinline__ void mma_f16(float* d, const uint32_t* a, const uint32_t* b) {
    asm volatile(
        "mma.sync.aligned.m16n8k16.row.col.f32.f16.f16.f32 "
        "{%0,%1,%2,%3}, {%4,%5,%6,%7}, {%8,%9}, {%0,%1,%2,%3};"
        : "+f"(d[0]), "+f"(d[1]), "+f"(d[2]), "+f"(d[3])
        : "r"(a[0]), "r"(a[1]), "r"(a[2]), "r"(a[3]), "r"(b[0]), "r"(b[1]));
}

__device__ __forceinline__ void ldsm_x4(uint32_t& r0, uint32_t& r1, uint32_t& r2, uint32_t& r3,
                                        uint32_t addr) {
    asm volatile("ldmatrix.sync.aligned.m8n8.x4.shared.b16 {%0,%1,%2,%3}, [%4];"
                 : "=r"(r0), "=r"(r1), "=r"(r2), "=r"(r3) : "r"(addr));
}
__device__ __forceinline__ void ldsm_x2(uint32_t& r0, uint32_t& r1, uint32_t addr) {
    asm volatile("ldmatrix.sync.aligned.m8n8.x2.shared.b16 {%0,%1}, [%2];"
                 : "=r"(r0), "=r"(r1) : "r"(addr));
}

__device__ __forceinline__ uint32_t smem_u32(const void* p) {
    uint32_t a;
    asm("{ .reg .u64 t; cvta.to.shared.u64 t, %1; cvt.u32.u64 %0, t; }" : "=r"(a) : "l"(p));
    return a;
}

__device__ __forceinline__ void cp16(uint32_t dst, const void* src, bool pred) {
    const int sz = pred ? 16 : 0;
    asm volatile("cp.async.cg.shared.global [%0], [%1], 16, %2;"
                 :: "r"(dst), "l"(src), "r"(sz) : "memory");
}
#define CP_COMMIT() asm volatile("cp.async.commit_group;" ::: "memory")
#define CP_WAIT1()  asm volatile("cp.async.wait_group 1;" ::: "memory")
#define CP_WAIT0()  asm volatile("cp.async.wait_group 0;" ::: "memory")

__device__ __forceinline__ uint32_t ex2_f16x2(__half2 x) {
    uint32_t r;
    asm("ex2.approx.f16x2 %0, %1;" : "=r"(r) : "r"(*(uint32_t*)&x));
    return r;
}

// ============================================================================
// Kernel 0a: fp32 -> fp16 convert.
// ============================================================================
__global__ __launch_bounds__(256) void cvt_x_kernel(
    const float* __restrict__ src, __half* __restrict__ dst, int n8)
{
    const int i = blockIdx.x * 256 + threadIdx.x;
    if (i >= n8) return;
    const float4 a = ((const float4*)src)[2 * i];
    const float4 b = ((const float4*)src)[2 * i + 1];
    __half2 h0 = __floats2half2_rn(a.x, a.y);
    __half2 h1 = __floats2half2_rn(a.z, a.w);
    __half2 h2 = __floats2half2_rn(b.x, b.y);
    __half2 h3 = __floats2half2_rn(b.z, b.w);
    uint4 u;
    u.x = *(uint32_t*)&h0; u.y = *(uint32_t*)&h1;
    u.z = *(uint32_t*)&h2; u.w = *(uint32_t*)&h3;
    ((uint4*)dst)[i] = u;
}

// ============================================================================
// Kernel 0b: fused weight convert.
// ============================================================================
__global__ __launch_bounds__(256) void cvt_w_kernel(
    const float* __restrict__ wq, const float* __restrict__ wk,
    const float* __restrict__ wv, __half* __restrict__ dst)
{
    const int nw8 = D * D / 8;
    const int i = blockIdx.x * 256 + threadIdx.x;
    if (i >= 3 * nw8) return;
    const float* src;
    int j;
    if (i < nw8)          { src = wq; j = i; }
    else if (i < 2 * nw8) { src = wk; j = i - nw8; }
    else                  { src = wv; j = i - 2 * nw8; }
    const float4 a = ((const float4*)src)[2 * j];
    const float4 b = ((const float4*)src)[2 * j + 1];
    __half2 h0 = __floats2half2_rn(a.x, a.y);
    __half2 h1 = __floats2half2_rn(a.z, a.w);
    __half2 h2 = __floats2half2_rn(b.x, b.y);
    __half2 h3 = __floats2half2_rn(b.z, b.w);
    uint4 u;
    u.x = *(uint32_t*)&h0; u.y = *(uint32_t*)&h1;
    u.z = *(uint32_t*)&h2; u.w = *(uint32_t*)&h3;
    ((uint4*)dst)[i] = u;
}

// ============================================================================
// Kernel 0c: zero g_vt tail.
// ============================================================================
__global__ __launch_bounds__(256) void vt_pad_kernel()
{
    const int i = blockIdx.x * 256 + threadIdx.x;
    if (i >= B * H * HD * 16) return;
    const int row = i >> 4, j = i & 15;
    ((uint2*)(g_vt + (size_t)row * VT_PITCH + 192))[j] = make_uint2(0u, 0u);
}

// ============================================================================
// Kernel 1: QKV projection (unchanged from R13 winner).
// ============================================================================
#define HPITCH 72
#define A_HALVES (128 * HPITCH)
#define BQ_HALVES (128 * HPITCH)
#define STAGE_HALVES (A_HALVES + BQ_HALVES)
#define STAGE_BYTES (STAGE_HALVES * 2)          // 36864
#define SMEM_QKV_BYTES (3 * STAGE_BYTES)        // 110592
#define NCHUNK 12

__global__ __launch_bounds__(256, 2) void qkv_mma_kernel(
    const float* __restrict__ bq, const float* __restrict__ bv, int mblk0)
{
    extern __shared__ __half smh[];
    const uint32_t sbase = smem_u32(smh);

    const int tid  = threadIdx.x;
    const int lane = tid & 31;
    const int wid  = tid >> 5;
    const int g    = lane >> 2;
    const int t    = lane & 3;
    const int wm   = wid & 1;
    const int wn   = wid >> 1;

    const int m0  = (mblk0 + blockIdx.x) * 128;
    const int n0g = blockIdx.y * 128;
    const int proj = n0g / 768;
    const int n0   = n0g - proj * 768;

    const float* bias = (proj == 0) ? bq : ((proj == 2) ? bv : nullptr);

    const int lrow = tid >> 3;
    const int lcg  = tid & 7;

    auto issue = [&](int c, int s) {
        const int k0 = c * 64;
        const uint32_t smA = sbase + s * STAGE_BYTES;
        const uint32_t smB = smA + A_HALVES * 2;
#pragma unroll
        for (int i = 0; i < 4; ++i) {
            const int row = lrow + i * 32;
            const int m = m0 + row;
            const bool pa = m < M_TOT;
            const __half* srcA = g_xh + (size_t)(pa ? m : 0) * 768 + k0 + lcg * 8;
            cp16(smA + (row * HPITCH + lcg * 8) * 2, srcA, pa);
        }
#pragma unroll
        for (int i = 0; i < 4; ++i) {
            const int row = lrow + i * 32;
            const __half* srcB = g_wh + (size_t)(n0g + row) * 768 + k0 + lcg * 8;
            cp16(smB + (row * HPITCH + lcg * 8) * 2, srcB, true);
        }
        CP_COMMIT();
    };

    issue(0, 0);
    issue(1, 1);

    const int a_row_l = (lane & 7) + ((lane >> 3) & 1) * 8;
    const int a_col_l = ((lane >> 4) & 1) * 8;
    const int b_row_l = (lane & 7) + ((lane >> 4) & 1) * 8;
    const int b_col_l = ((lane >> 3) & 1) * 8;

    float acc[4][4][4];
#pragma unroll
    for (int mt = 0; mt < 4; ++mt)
#pragma unroll
        for (int nt = 0; nt < 4; ++nt)
#pragma unroll
            for (int e = 0; e < 4; ++e) acc[mt][nt][e] = 0.f;

    for (int c = 0; c < NCHUNK; ++c) {
        CP_WAIT1();
        __syncthreads();
        if (c + 2 < NCHUNK) issue(c + 2, (c + 2) % 3);

        const uint32_t stA = sbase + (c % 3) * STAGE_BYTES;
        const uint32_t stB = stA + A_HALVES * 2;
#pragma unroll
        for (int ks = 0; ks < 4; ++ks) {
            uint32_t af[4][4], bf[4][2];
#pragma unroll
            for (int mt = 0; mt < 4; ++mt) {
                const uint32_t addr = stA +
                    ((wm * 64 + mt * 16 + a_row_l) * HPITCH + ks * 16 + a_col_l) * 2;
                ldsm_x4(af[mt][0], af[mt][1], af[mt][2], af[mt][3], addr);
            }
#pragma unroll
            for (int ntp = 0; ntp < 2; ++ntp) {
                const uint32_t addr = stB +
                    ((wn * 32 + ntp * 16 + b_row_l) * HPITCH + ks * 16 + b_col_l) * 2;
                ldsm_x4(bf[2 * ntp][0], bf[2 * ntp][1],
                        bf[2 * ntp + 1][0], bf[2 * ntp + 1][1], addr);
            }
#pragma unroll
            for (int mt = 0; mt < 4; ++mt)
#pragma unroll
                for (int nt = 0; nt < 4; ++nt)
                    mma_f16(acc[mt][nt], af[mt], bf[nt]);
        }
    }

    const float scale = (proj == 0) ? 0.125f : 1.0f;
#pragma unroll
    for (int mt = 0; mt < 4; ++mt) {
        const int r0 = m0 + wm * 64 + mt * 16 + g;
#pragma unroll
        for (int nt = 0; nt < 4; ++nt) {
            const int n = n0 + wn * 32 + nt * 8 + t * 2;
            const int hh = n >> 6;
            const int hd = n & 63;
            float bx = 0.f, by = 0.f;
            if (bias) { bx = bias[n]; by = bias[n + 1]; }
#pragma unroll
            for (int half_i = 0; half_i < 2; ++half_i) {
                const int m = r0 + half_i * 8;
                if (m >= M_TOT) continue;
                const int bb = m / S;
                const int ss = m - bb * S;
                const int bh = bb * H + hh;
                const float vx = (acc[mt][nt][half_i * 2 + 0] + bx) * scale;
                const float vy = (acc[mt][nt][half_i * 2 + 1] + by) * scale;
                if (proj == 2) {
                    g_vt[((size_t)bh * HD + hd) * VT_PITCH + ss]     = __float2half_rn(vx);
                    g_vt[((size_t)bh * HD + hd + 1) * VT_PITCH + ss] = __float2half_rn(vy);
                } else {
                    __half2 hv = __floats2half2_rn(vx, vy);
                    __half* dst = (proj == 0) ? g_qh : g_kh;
                    *(__half2*)(dst + ((size_t)bh * S + ss) * HD + hd) = hv;
                }
            }
        }
    }
}

// ============================================================================
// Kernel 2: bias expand (fp16, pitch 198).
// ============================================================================
__global__ __launch_bounds__(256) void bias_expand_kernel(
    const float* __restrict__ bias_table, const int* __restrict__ rel_index)
{
    const int i = blockIdx.x * 256 + threadIdx.x;
    if (i >= S * S) return;
    const int q = i / S, k = i - q * S;
    const int r = rel_index[i];
#pragma unroll
    for (int h = 0; h < H; ++h)
        g_bias[((size_t)h * S + q) * BP + k] = __float2half_rn(bias_table[r * H + h]);
}

// ============================================================================
// Kernel 3: flash attention. kt=1 tile trimmed: NJ=10 n-tiles (keys 128..207,
// masked >=197), P.V ks<5 (P cols 0..79; cols 72..79 are j=9's masked zeros,
// freshly written this tile — no stale reads).
// ============================================================================
#define FK_PITCH 72
#define FP_PITCH 136
#define K_HALVES (128 * FK_PITCH)
#define V_HALVES (72 * FP_PITCH)
#define FV_BASE (2 * K_HALVES)
#define FP_BASE (2 * K_HALVES + 2 * V_HALVES)
#define SMEM_FLASH_BYTES ((FP_BASE + 128 * FP_PITCH) * 2)   // 110848

__global__ __launch_bounds__(256, 2) void flash_kernel(float* __restrict__ out, int bh0)
{
    extern __shared__ __half smh[];
    const uint32_t sbase = smem_u32(smh);

    const int tid  = threadIdx.x;
    const int lane = tid & 31;
    const int wid  = tid >> 5;
    const int g    = lane >> 2;
    const int t    = lane & 3;

    const int qt = blockIdx.x;
    const int bh = bh0 + blockIdx.y;
    const int b  = bh / H;
    const int h  = bh - b * H;
    const int qbase = qt * 128;
    const int wrow  = wid * 16;

    const int a_row_l = (lane & 7) + ((lane >> 3) & 1) * 8;
    const int a_col_l = ((lane >> 4) & 1) * 8;
    const int b_row_l = (lane & 7) + ((lane >> 4) & 1) * 8;
    const int b_col_l = ((lane >> 3) & 1) * 8;

    const __half* Qg = g_qh + (size_t)bh * S * HD;
    const __half* Kg = g_kh + (size_t)bh * S * HD;
    const __half* Vt = g_vt + (size_t)bh * HD * VT_PITCH;

#pragma unroll
    for (int kt = 0; kt < 2; ++kt) {
        const int kb = kt * 128;
        const uint32_t smK = sbase + kt * K_HALVES * 2;
        const uint32_t smV = sbase + (FV_BASE + kt * V_HALVES) * 2;
#pragma unroll
        for (int it = 0; it < 4; ++it) {
            const int f = tid + it * 256;
            const int row = f >> 3, cg = f & 7;
            const int kk = kb + row;
            const bool p = kk < S;
            cp16(smK + (row * FK_PITCH + cg * 8) * 2,
                 Kg + (size_t)(p ? kk : 0) * HD + cg * 8, p);
        }
#pragma unroll
        for (int it = 0; it < 4; ++it) {
            const int f = tid + it * 256;
            const int row = f >> 4, cg = f & 15;
            cp16(smV + (row * FP_PITCH + cg * 8) * 2,
                 Vt + (size_t)row * VT_PITCH + kb + cg * 8, true);
        }
        CP_COMMIT();
    }

    {
        const __half one  = __float2half(1.f);
        const __half zero = __float2half(0.f);
        for (int i = tid; i < 2 * 8 * FP_PITCH; i += 256) {
            const int buf = i / (8 * FP_PITCH);
            const int rem = i - buf * 8 * FP_PITCH;
            const int r   = rem / FP_PITCH;
            const int cc  = rem - r * FP_PITCH;
            smh[FV_BASE + buf * V_HALVES + (64 + r) * FP_PITCH + cc] = (r == 0) ? one : zero;
        }
    }

    {
        __half* sQ = smh + FP_BASE;
#pragma unroll
        for (int it = 0; it < 4; ++it) {
            const int f = tid + it * 256;
            const int row = f >> 3, cg = f & 7;
            const int m = qbase + row;
            uint4 u = make_uint4(0u, 0u, 0u, 0u);
            if (m < S) u = *(const uint4*)(Qg + (size_t)m * HD + cg * 8);
            *(uint4*)(sQ + row * FK_PITCH + cg * 8) = u;
        }
    }
    __syncthreads();

    uint32_t qf[4][4];
    {
        const uint32_t sQ = sbase + FP_BASE * 2;
#pragma unroll
        for (int ks = 0; ks < 4; ++ks) {
            const uint32_t addr = sQ + ((wrow + a_row_l) * FK_PITCH + ks * 16 + a_col_l) * 2;
            ldsm_x4(qf[ks][0], qf[ks][1], qf[ks][2], qf[ks][3], addr);
        }
    }
    __syncthreads();

    const int qr0 = qbase + wrow + g;
    const int qr1 = qr0 + 8;
    const __half* brow0 = g_bias + ((size_t)h * S + min(qr0, S - 1)) * BP;
    const __half* brow1 = g_bias + ((size_t)h * S + min(qr1, S - 1)) * BP;

    float m0r = -1e30f, m1r = -1e30f;
    float o[9][4];
#pragma unroll
    for (int j = 0; j < 9; ++j)
#pragma unroll
        for (int e = 0; e < 4; ++e) o[j][e] = 0.f;

#pragma unroll
    for (int kt = 0; kt < 2; ++kt) {
        const int kb = kt * 128;
        // kt-dependent trim (constants after unroll):
        const int NJ   = kt ? 10 : 16;   // QK n-tiles (8 keys each)
        const int NJP  = kt ? 5 : 8;     // K-fragment ldsm pairs
        const int NPKS = kt ? 5 : 8;     // P.V k16 steps (16 P-cols each)

        if (kt == 0) { CP_WAIT1(); } else { CP_WAIT0(); }
        __syncthreads();

        const uint32_t sK = sbase + kt * K_HALVES * 2;
        const uint32_t sV = sbase + (FV_BASE + kt * V_HALVES) * 2;

        float sacc[16][4];
#pragma unroll
        for (int j = 0; j < 16; ++j)
#pragma unroll
            for (int e = 0; e < 4; ++e) sacc[j][e] = 0.f;

#pragma unroll
        for (int ks = 0; ks < 4; ++ks) {
            uint32_t bf[16][2];
#pragma unroll
            for (int jp = 0; jp < NJP; ++jp) {
                const uint32_t addr = sK +
                    ((jp * 16 + b_row_l) * FK_PITCH + ks * 16 + b_col_l) * 2;
                ldsm_x4(bf[2 * jp][0], bf[2 * jp][1],
                        bf[2 * jp + 1][0], bf[2 * jp + 1][1], addr);
            }
#pragma unroll
            for (int j = 0; j < NJ; ++j)
                mma_f16(sacc[j], qf[ks], bf[j]);
        }

#pragma unroll
        for (int j = 0; j < NJ; ++j) {
            const int kc = kb + j * 8 + 2 * t;
            if (kc < S) {
                const float2 b0 = __half22float2(*(const __half2*)(brow0 + kc));
                const float2 b1 = __half22float2(*(const __half2*)(brow1 + kc));
                sacc[j][0] += b0.x;
                sacc[j][1] = (kc + 1 < S) ? sacc[j][1] + b0.y : -1e30f;
                sacc[j][2] += b1.x;
                sacc[j][3] = (kc + 1 < S) ? sacc[j][3] + b1.y : -1e30f;
            } else {
                sacc[j][0] = -1e30f; sacc[j][1] = -1e30f;
                sacc[j][2] = -1e30f; sacc[j][3] = -1e30f;
            }
        }

        float mx0 = -1e30f, mx1 = -1e30f;
#pragma unroll
        for (int j = 0; j < NJ; ++j) {
            mx0 = fmaxf(mx0, fmaxf(sacc[j][0], sacc[j][1]));
            mx1 = fmaxf(mx1, fmaxf(sacc[j][2], sacc[j][3]));
        }
        mx0 = fmaxf(mx0, __shfl_xor_sync(0xffffffffu, mx0, 1));
        mx0 = fmaxf(mx0, __shfl_xor_sync(0xffffffffu, mx0, 2));
        mx1 = fmaxf(mx1, __shfl_xor_sync(0xffffffffu, mx1, 1));
        mx1 = fmaxf(mx1, __shfl_xor_sync(0xffffffffu, mx1, 2));

        const float nm0 = fmaxf(m0r, mx0);
        const float nm1 = fmaxf(m1r, mx1);
        const float sc0 = __expf(m0r - nm0);
        const float sc1 = __expf(m1r - nm1);
        m0r = nm0; m1r = nm1;

        const float c0 = -nm0 * LOG2E;
        const float c1 = -nm1 * LOG2E;
        __half* sPp = smh + FP_BASE;
#pragma unroll
        for (int j = 0; j < NJ; ++j) {
            const int col = j * 8 + 2 * t;
            __half2 a0 = __floats2half2_rn(fmaf(sacc[j][0], LOG2E, c0),
                                           fmaf(sacc[j][1], LOG2E, c0));
            __half2 a1 = __floats2half2_rn(fmaf(sacc[j][2], LOG2E, c1),
                                           fmaf(sacc[j][3], LOG2E, c1));
            *(uint32_t*)(sPp + (wrow + g) * FP_PITCH + col)     = ex2_f16x2(a0);
            *(uint32_t*)(sPp + (wrow + g + 8) * FP_PITCH + col) = ex2_f16x2(a1);
        }

#pragma unroll
        for (int j = 0; j < 9; ++j) {
            o[j][0] *= sc0; o[j][1] *= sc0;
            o[j][2] *= sc1; o[j][3] *= sc1;
        }
        __syncwarp();

        const uint32_t sP = sbase + FP_BASE * 2;
#pragma unroll
        for (int ks = 0; ks < NPKS; ++ks) {
            uint32_t af[4];
            {
                const uint32_t addr = sP +
                    ((wrow + a_row_l) * FP_PITCH + ks * 16 + a_col_l) * 2;
                ldsm_x4(af[0], af[1], af[2], af[3], addr);
            }
            uint32_t bf[9][2];
#pragma unroll
            for (int jp = 0; jp < 4; ++jp) {
                const uint32_t addr = sV +
                    ((jp * 16 + b_row_l) * FP_PITCH + ks * 16 + b_col_l) * 2;
                ldsm_x4(bf[2 * jp][0], bf[2 * jp][1],
                        bf[2 * jp + 1][0], bf[2 * jp + 1][1], addr);
            }
            {
                const uint32_t addr = sV +
                    ((64 + (b_row_l & 7)) * FP_PITCH + ks * 16 + b_col_l) * 2;
                ldsm_x2(bf[8][0], bf[8][1], addr);
            }
#pragma unroll
            for (int j = 0; j < 9; ++j)
                mma_f16(o[j], af, bf[j]);
        }
        __syncwarp();
    }

    const float l0 = __shfl_sync(0xffffffffu, o[8][0], lane & ~3);
    const float l1 = __shfl_sync(0xffffffffu, o[8][2], lane & ~3);
    const float inv0 = 1.f / l0;
    const float inv1 = 1.f / l1;
#pragma unroll
    for (int j = 0; j < 8; ++j) {
        const int col = h * HD + j * 8 + 2 * t;
        if (qr0 < S) {
            float2 v; v.x = o[j][0] * inv0; v.y = o[j][1] * inv0;
            *(float2*)(out + ((size_t)b * S + qr0) * D + col) = v;
        }
        if (qr1 < S) {
            float2 v; v.x = o[j][2] * inv1; v.y = o[j][3] * inv1;
            *(float2*)(out + ((size_t)b * S + qr1) * D + col) = v;
        }
    }
}

// ============================================================================
// Launch: batch-split pipeline (unchanged from R13 winner).
// ============================================================================
extern "C" void kernel_launch(void* const* d_in, const int* in_sizes, int n_in,
                              void* d_out, int out_size)
{
    const float* X  = (const float*)d_in[0];
    const float* wq = (const float*)d_in[1];
    const float* bq = (const float*)d_in[2];
    const float* wk = (const float*)d_in[3];
    const float* wv = (const float*)d_in[4];
    const float* bv = (const float*)d_in[5];
    const float* bt = (const float*)d_in[6];
    const int*   ri = (const int*)d_in[7];
    float* out = (float*)d_out;

    (void)in_sizes; (void)n_in; (void)out_size;

    static __half* xh_ptr = nullptr;
    static __half* wh_ptr = nullptr;
    static cudaStream_t s1 = nullptr;
    static cudaEvent_t ev_fork, ev_prep, ev_xb, ev_a, ev_f;
    if (!xh_ptr) {
        cudaGetSymbolAddress((void**)&xh_ptr, g_xh);
        cudaGetSymbolAddress((void**)&wh_ptr, g_wh);
        cudaFuncSetAttribute(qkv_mma_kernel, cudaFuncAttributeMaxDynamicSharedMemorySize, SMEM_QKV_BYTES);
        cudaFuncSetAttribute(flash_kernel, cudaFuncAttributeMaxDynamicSharedMemorySize, SMEM_FLASH_BYTES);
        cudaStreamCreateWithFlags(&s1, cudaStreamNonBlocking);
        cudaEventCreateWithFlags(&ev_fork, cudaEventDisableTiming);
        cudaEventCreateWithFlags(&ev_prep, cudaEventDisableTiming);
        cudaEventCreateWithFlags(&ev_xb,   cudaEventDisableTiming);
        cudaEventCreateWithFlags(&ev_a,    cudaEventDisableTiming);
        cudaEventCreateWithFlags(&ev_f,    cudaEventDisableTiming);
    }

    const int nx8a = ROWS_A * D / 8;
    const int nx8b = (M_TOT - ROWS_A) * D / 8;
    const int nw8  = 3 * D * D / 8;

    cudaEventRecord(ev_fork, 0);
    cudaStreamWaitEvent(s1, ev_fork, 0);

    cvt_x_kernel<<<(nx8a + 255) / 256, 256>>>(X, xh_ptr, nx8a);

    cvt_w_kernel<<<(nw8 + 255) / 256, 256, 0, s1>>>(wq, wk, wv, wh_ptr);
    vt_pad_kernel<<<(B * H * HD * 16 + 255) / 256, 256, 0, s1>>>();
    bias_expand_kernel<<<(S * S + 255) / 256, 256, 0, s1>>>(bt, ri);
    cudaEventRecord(ev_prep, s1);
    cvt_x_kernel<<<(nx8b + 255) / 256, 256, 0, s1>>>(
        X + (size_t)ROWS_A * D, xh_ptr + (size_t)ROWS_A * D, nx8b);
    cudaEventRecord(ev_xb, s1);

    cudaStreamWaitEvent(0, ev_prep, 0);
    qkv_mma_kernel<<<dim3(MBLK_A, 18), 256, SMEM_QKV_BYTES>>>(bq, bv, 0);
    cudaEventRecord(ev_a, 0);

    cudaStreamWaitEvent(0, ev_xb, 0);
    qkv_mma_kernel<<<dim3(MBLK_B, 18), 256, SMEM_QKV_BYTES>>>(bq, bv, MBLK_A);

    cudaStreamWaitEvent(s1, ev_a, 0);
    flash_kernel<<<dim3(2, 32 * H), 256, SMEM_FLASH_BYTES, s1>>>(out, 0);
    cudaEventRecord(ev_f, s1);

    flash_kernel<<<dim3(2, 32 * H), 256, SMEM_FLASH_BYTES>>>(out, 32 * H);

    cudaStreamWaitEvent(0, ev_f, 0);
}

// round 15
// speedup vs baseline: 2.0088x; 2.0088x over previous
#include <cuda_runtime.h>
#include <cuda_fp16.h>
#include <math.h>
#include <cstdint>

#define B 64
#define S 197
#define D 768
#define H 12
#define HD 64
#define M_TOT (B * S)          // 12608
#define NUM_REL 732
#define VT_PITCH 256
#define BP 198
#define LOG2E 1.44269504f

#define MBLK_A 50
#define MBLK_B 49
#define ROWS_A 6400

// -------- device scratch --------
__device__ __half g_xh[(size_t)M_TOT * D];
__device__ __half g_wh[(size_t)3 * D * D];
__device__ __half g_qh[(size_t)B * H * S * HD];
__device__ __half g_kh[(size_t)B * H * S * HD];
__device__ __half g_vt[(size_t)B * H * HD * VT_PITCH];
__device__ __half g_bias[(size_t)H * S * BP];

__device__ __forceinline__ void mma_f16(float* d, const uint32_t* a, const uint32_t* b) {
    asm volatile(
        "mma.sync.aligned.m16n8k16.row.col.f32.f16.f16.f32 "
        "{%0,%1,%2,%3}, {%4,%5,%6,%7}, {%8,%9}, {%0,%1,%2,%3};"
        : "+f"(d[0]), "+f"(d[1]), "+f"(d[2]), "+f"(d[3])
        : "r"(a[0]), "r"(a[1]), "r"(a[2]), "r"(a[3]), "r"(b[0]), "r"(b[1]));
}

__device__ __forceinline__ void ldsm_x4(uint32_t& r0, uint32_t& r1, uint32_t& r2, uint32_t& r3,
                                        uint32_t addr) {
    asm volatile("ldmatrix.sync.aligned.m8n8.x4.shared.b16 {%0,%1,%2,%3}, [%4];"
                 : "=r"(r0), "=r"(r1), "=r"(r2), "=r"(r3) : "r"(addr));
}
__device__ __forceinline__ void ldsm_x2(uint32_t& r0, uint32_t& r1, uint32_t addr) {
    asm volatile("ldmatrix.sync.aligned.m8n8.x2.shared.b16 {%0,%1}, [%2];"
                 : "=r"(r0), "=r"(r1) : "r"(addr));
}

__device__ __forceinline__ uint32_t smem_u32(const void* p) {
    uint32_t a;
    asm("{ .reg .u64 t; cvta.to.shared.u64 t, %1; cvt.u32.u64 %0, t; }" : "=r"(a) : "l"(p));
    return a;
}

__device__ __forceinline__ void cp16(uint32_t dst, const void* src, bool pred) {
    const int sz = pred ? 16 : 0;
    asm volatile("cp.async.cg.shared.global [%0], [%1], 16, %2;"
                 :: "r"(dst), "l"(src), "r"(sz) : "memory");
}
#define CP_COMMIT() asm volatile("cp.async.commit_group;" ::: "memory")
#define CP_WAIT1()  asm volatile("cp.async.wait_group 1;" ::: "memory")
#define CP_WAIT0()  asm volatile("cp.async.wait_group 0;" ::: "memory")

__device__ __forceinline__ uint32_t ex2_f16x2(__half2 x) {
    uint32_t r;
    asm("ex2.approx.f16x2 %0, %1;" : "=r"(r) : "r"(*(uint32_t*)&x));
    return r;
}

// ============================================================================
// Kernel 0a: fp32 -> fp16 convert.
// ============================================================================
__global__ __launch_bounds__(256) void cvt_x_kernel(
    const float* __restrict__ src, __half* __restrict__ dst, int n8)
{
    const int i = blockIdx.x * 256 + threadIdx.x;
    if (i >= n8) return;
    const float4 a = ((const float4*)src)[2 * i];
    const float4 b = ((const float4*)src)[2 * i + 1];
    __half2 h0 = __floats2half2_rn(a.x, a.y);
    __half2 h1 = __floats2half2_rn(a.z, a.w);
    __half2 h2 = __floats2half2_rn(b.x, b.y);
    __half2 h3 = __floats2half2_rn(b.z, b.w);
    uint4 u;
    u.x = *(uint32_t*)&h0; u.y = *(uint32_t*)&h1;
    u.z = *(uint32_t*)&h2; u.w = *(uint32_t*)&h3;
    ((uint4*)dst)[i] = u;
}

// ============================================================================
// Kernel 0b: fused weight convert.
// ============================================================================
__global__ __launch_bounds__(256) void cvt_w_kernel(
    const float* __restrict__ wq, const float* __restrict__ wk,
    const float* __restrict__ wv, __half* __restrict__ dst)
{
    const int nw8 = D * D / 8;
    const int i = blockIdx.x * 256 + threadIdx.x;
    if (i >= 3 * nw8) return;
    const float* src;
    int j;
    if (i < nw8)          { src = wq; j = i; }
    else if (i < 2 * nw8) { src = wk; j = i - nw8; }
    else                  { src = wv; j = i - 2 * nw8; }
    const float4 a = ((const float4*)src)[2 * j];
    const float4 b = ((const float4*)src)[2 * j + 1];
    __half2 h0 = __floats2half2_rn(a.x, a.y);
    __half2 h1 = __floats2half2_rn(a.z, a.w);
    __half2 h2 = __floats2half2_rn(b.x, b.y);
    __half2 h3 = __floats2half2_rn(b.z, b.w);
    uint4 u;
    u.x = *(uint32_t*)&h0; u.y = *(uint32_t*)&h1;
    u.z = *(uint32_t*)&h2; u.w = *(uint32_t*)&h3;
    ((uint4*)dst)[i] = u;
}

// ============================================================================
// Kernel 0c: zero g_vt tail.
// ============================================================================
__global__ __launch_bounds__(256) void vt_pad_kernel()
{
    const int i = blockIdx.x * 256 + threadIdx.x;
    if (i >= B * H * HD * 16) return;
    const int row = i >> 4, j = i & 15;
    ((uint2*)(g_vt + (size_t)row * VT_PITCH + 192))[j] = make_uint2(0u, 0u);
}

// ============================================================================
// Kernel 1: QKV projection (unchanged from R13 winner).
// ============================================================================
#define HPITCH 72
#define A_HALVES (128 * HPITCH)
#define BQ_HALVES (128 * HPITCH)
#define STAGE_HALVES (A_HALVES + BQ_HALVES)
#define STAGE_BYTES (STAGE_HALVES * 2)          // 36864
#define SMEM_QKV_BYTES (3 * STAGE_BYTES)        // 110592
#define NCHUNK 12

__global__ __launch_bounds__(256, 2) void qkv_mma_kernel(
    const float* __restrict__ bq, const float* __restrict__ bv, int mblk0)
{
    extern __shared__ __half smh[];
    const uint32_t sbase = smem_u32(smh);

    const int tid  = threadIdx.x;
    const int lane = tid & 31;
    const int wid  = tid >> 5;
    const int g    = lane >> 2;
    const int t    = lane & 3;
    const int wm   = wid & 1;
    const int wn   = wid >> 1;

    const int m0  = (mblk0 + blockIdx.x) * 128;
    const int n0g = blockIdx.y * 128;
    const int proj = n0g / 768;
    const int n0   = n0g - proj * 768;

    const float* bias = (proj == 0) ? bq : ((proj == 2) ? bv : nullptr);

    const int lrow = tid >> 3;
    const int lcg  = tid & 7;

    auto issue = [&](int c, int s) {
        const int k0 = c * 64;
        const uint32_t smA = sbase + s * STAGE_BYTES;
        const uint32_t smB = smA + A_HALVES * 2;
#pragma unroll
        for (int i = 0; i < 4; ++i) {
            const int row = lrow + i * 32;
            const int m = m0 + row;
            const bool pa = m < M_TOT;
            const __half* srcA = g_xh + (size_t)(pa ? m : 0) * 768 + k0 + lcg * 8;
            cp16(smA + (row * HPITCH + lcg * 8) * 2, srcA, pa);
        }
#pragma unroll
        for (int i = 0; i < 4; ++i) {
            const int row = lrow + i * 32;
            const __half* srcB = g_wh + (size_t)(n0g + row) * 768 + k0 + lcg * 8;
            cp16(smB + (row * HPITCH + lcg * 8) * 2, srcB, true);
        }
        CP_COMMIT();
    };

    issue(0, 0);
    issue(1, 1);

    const int a_row_l = (lane & 7) + ((lane >> 3) & 1) * 8;
    const int a_col_l = ((lane >> 4) & 1) * 8;
    const int b_row_l = (lane & 7) + ((lane >> 4) & 1) * 8;
    const int b_col_l = ((lane >> 3) & 1) * 8;

    float acc[4][4][4];
#pragma unroll
    for (int mt = 0; mt < 4; ++mt)
#pragma unroll
        for (int nt = 0; nt < 4; ++nt)
#pragma unroll
            for (int e = 0; e < 4; ++e) acc[mt][nt][e] = 0.f;

    for (int c = 0; c < NCHUNK; ++c) {
        CP_WAIT1();
        __syncthreads();
        if (c + 2 < NCHUNK) issue(c + 2, (c + 2) % 3);

        const uint32_t stA = sbase + (c % 3) * STAGE_BYTES;
        const uint32_t stB = stA + A_HALVES * 2;
#pragma unroll
        for (int ks = 0; ks < 4; ++ks) {
            uint32_t af[4][4], bf[4][2];
#pragma unroll
            for (int mt = 0; mt < 4; ++mt) {
                const uint32_t addr = stA +
                    ((wm * 64 + mt * 16 + a_row_l) * HPITCH + ks * 16 + a_col_l) * 2;
                ldsm_x4(af[mt][0], af[mt][1], af[mt][2], af[mt][3], addr);
            }
#pragma unroll
            for (int ntp = 0; ntp < 2; ++ntp) {
                const uint32_t addr = stB +
                    ((wn * 32 + ntp * 16 + b_row_l) * HPITCH + ks * 16 + b_col_l) * 2;
                ldsm_x4(bf[2 * ntp][0], bf[2 * ntp][1],
                        bf[2 * ntp + 1][0], bf[2 * ntp + 1][1], addr);
            }
#pragma unroll
            for (int mt = 0; mt < 4; ++mt)
#pragma unroll
                for (int nt = 0; nt < 4; ++nt)
                    mma_f16(acc[mt][nt], af[mt], bf[nt]);
        }
    }

    const float scale = (proj == 0) ? 0.125f : 1.0f;
#pragma unroll
    for (int mt = 0; mt < 4; ++mt) {
        const int r0 = m0 + wm * 64 + mt * 16 + g;
#pragma unroll
        for (int nt = 0; nt < 4; ++nt) {
            const int n = n0 + wn * 32 + nt * 8 + t * 2;
            const int hh = n >> 6;
            const int hd = n & 63;
            float bx = 0.f, by = 0.f;
            if (bias) { bx = bias[n]; by = bias[n + 1]; }
#pragma unroll
            for (int half_i = 0; half_i < 2; ++half_i) {
                const int m = r0 + half_i * 8;
                if (m >= M_TOT) continue;
                const int bb = m / S;
                const int ss = m - bb * S;
                const int bh = bb * H + hh;
                const float vx = (acc[mt][nt][half_i * 2 + 0] + bx) * scale;
                const float vy = (acc[mt][nt][half_i * 2 + 1] + by) * scale;
                if (proj == 2) {
                    g_vt[((size_t)bh * HD + hd) * VT_PITCH + ss]     = __float2half_rn(vx);
                    g_vt[((size_t)bh * HD + hd + 1) * VT_PITCH + ss] = __float2half_rn(vy);
                } else {
                    __half2 hv = __floats2half2_rn(vx, vy);
                    __half* dst = (proj == 0) ? g_qh : g_kh;
                    *(__half2*)(dst + ((size_t)bh * S + ss) * HD + hd) = hv;
                }
            }
        }
    }
}

// ============================================================================
// Kernel 2: bias expand (fp16, pitch 198).
// ============================================================================
__global__ __launch_bounds__(256) void bias_expand_kernel(
    const float* __restrict__ bias_table, const int* __restrict__ rel_index)
{
    const int i = blockIdx.x * 256 + threadIdx.x;
    if (i >= S * S) return;
    const int q = i / S, k = i - q * S;
    const int r = rel_index[i];
#pragma unroll
    for (int h = 0; h < H; ++h)
        g_bias[((size_t)h * S + q) * BP + k] = __float2half_rn(bias_table[r * H + h]);
}

// ============================================================================
// Kernel 3: flash attention. Tile body stamped by macro with LITERAL bounds
// (R14's runtime bounds caused local-memory spills; literals restore full
// unroll + register residency). kt=1: 10 n-tiles / 5 ldsm pairs / 5 P.V ks.
// ============================================================================
#define FK_PITCH 72
#define FP_PITCH 136
#define K_HALVES (128 * FK_PITCH)
#define V_HALVES (72 * FP_PITCH)
#define FV_BASE (2 * K_HALVES)
#define FP_BASE (2 * K_HALVES + 2 * V_HALVES)
#define SMEM_FLASH_BYTES ((FP_BASE + 128 * FP_PITCH) * 2)   // 110848

// All loop bounds below are macro-substituted literals -> full unroll.
#define FLASH_TILE(KT, NJ, NJP, NPKS)                                          \
    {                                                                          \
        const int kb = (KT) * 128;                                             \
        if ((KT) == 0) { CP_WAIT1(); } else { CP_WAIT0(); }                    \
        __syncthreads();                                                       \
        const uint32_t sK = sbase + (KT) * K_HALVES * 2;                       \
        const uint32_t sV = sbase + (FV_BASE + (KT) * V_HALVES) * 2;           \
        float sacc[NJ][4];                                                     \
        _Pragma("unroll")                                                      \
        for (int j = 0; j < (NJ); ++j)                                         \
            _Pragma("unroll")                                                  \
            for (int e = 0; e < 4; ++e) sacc[j][e] = 0.f;                      \
        _Pragma("unroll")                                                      \
        for (int ks = 0; ks < 4; ++ks) {                                       \
            uint32_t bf[NJ][2];                                                \
            _Pragma("unroll")                                                  \
            for (int jp = 0; jp < (NJP); ++jp) {                               \
                const uint32_t addr = sK +                                     \
                    ((jp * 16 + b_row_l) * FK_PITCH + ks * 16 + b_col_l) * 2;  \
                ldsm_x4(bf[2 * jp][0], bf[2 * jp][1],                          \
                        bf[2 * jp + 1][0], bf[2 * jp + 1][1], addr);           \
            }                                                                  \
            _Pragma("unroll")                                                  \
            for (int j = 0; j < (NJ); ++j)                                     \
                mma_f16(sacc[j], qf[ks], bf[j]);                               \
        }                                                                      \
        _Pragma("unroll")                                                      \
        for (int j = 0; j < (NJ); ++j) {                                       \
            const int kc = kb + j * 8 + 2 * t;                                 \
            if (kc < S) {                                                      \
                const float2 b0 = __half22float2(*(const __half2*)(brow0 + kc)); \
                const float2 b1 = __half22float2(*(const __half2*)(brow1 + kc)); \
                sacc[j][0] += b0.x;                                            \
                sacc[j][1] = (kc + 1 < S) ? sacc[j][1] + b0.y : -1e30f;        \
                sacc[j][2] += b1.x;                                            \
                sacc[j][3] = (kc + 1 < S) ? sacc[j][3] + b1.y : -1e30f;        \
            } else {                                                           \
                sacc[j][0] = -1e30f; sacc[j][1] = -1e30f;                      \
                sacc[j][2] = -1e30f; sacc[j][3] = -1e30f;                      \
            }                                                                  \
        }                                                                      \
        float mx0 = -1e30f, mx1 = -1e30f;                                      \
        _Pragma("unroll")                                                      \
        for (int j = 0; j < (NJ); ++j) {                                       \
            mx0 = fmaxf(mx0, fmaxf(sacc[j][0], sacc[j][1]));                   \
            mx1 = fmaxf(mx1, fmaxf(sacc[j][2], sacc[j][3]));                   \
        }                                                                      \
        mx0 = fmaxf(mx0, __shfl_xor_sync(0xffffffffu, mx0, 1));                \
        mx0 = fmaxf(mx0, __shfl_xor_sync(0xffffffffu, mx0, 2));                \
        mx1 = fmaxf(mx1, __shfl_xor_sync(0xffffffffu, mx1, 1));                \
        mx1 = fmaxf(mx1, __shfl_xor_sync(0xffffffffu, mx1, 2));                \
        const float nm0 = fmaxf(m0r, mx0);                                     \
        const float nm1 = fmaxf(m1r, mx1);                                     \
        const float sc0 = __expf(m0r - nm0);                                   \
        const float sc1 = __expf(m1r - nm1);                                   \
        m0r = nm0; m1r = nm1;                                                  \
        const float c0 = -nm0 * LOG2E;                                         \
        const float c1 = -nm1 * LOG2E;                                         \
        __half* sPp = smh + FP_BASE;                                           \
        _Pragma("unroll")                                                      \
        for (int j = 0; j < (NJ); ++j) {                                       \
            const int col = j * 8 + 2 * t;                                     \
            __half2 a0 = __floats2half2_rn(fmaf(sacc[j][0], LOG2E, c0),        \
                                           fmaf(sacc[j][1], LOG2E, c0));       \
            __half2 a1 = __floats2half2_rn(fmaf(sacc[j][2], LOG2E, c1),        \
                                           fmaf(sacc[j][3], LOG2E, c1));       \
            *(uint32_t*)(sPp + (wrow + g) * FP_PITCH + col)     = ex2_f16x2(a0); \
            *(uint32_t*)(sPp + (wrow + g + 8) * FP_PITCH + col) = ex2_f16x2(a1); \
        }                                                                      \
        _Pragma("unroll")                                                      \
        for (int j = 0; j < 9; ++j) {                                          \
            o[j][0] *= sc0; o[j][1] *= sc0;                                    \
            o[j][2] *= sc1; o[j][3] *= sc1;                                    \
        }                                                                      \
        __syncwarp();                                                          \
        const uint32_t sP = sbase + FP_BASE * 2;                               \
        _Pragma("unroll")                                                      \
        for (int ks = 0; ks < (NPKS); ++ks) {                                  \
            uint32_t af[4];                                                    \
            {                                                                  \
                const uint32_t addr = sP +                                     \
                    ((wrow + a_row_l) * FP_PITCH + ks * 16 + a_col_l) * 2;     \
                ldsm_x4(af[0], af[1], af[2], af[3], addr);                     \
            }                                                                  \
            uint32_t bfv[9][2];                                                \
            _Pragma("unroll")                                                  \
            for (int jp = 0; jp < 4; ++jp) {                                   \
                const uint32_t addr = sV +                                     \
                    ((jp * 16 + b_row_l) * FP_PITCH + ks * 16 + b_col_l) * 2;  \
                ldsm_x4(bfv[2 * jp][0], bfv[2 * jp][1],                        \
                        bfv[2 * jp + 1][0], bfv[2 * jp + 1][1], addr);         \
            }                                                                  \
            {                                                                  \
                const uint32_t addr = sV +                                     \
                    ((64 + (b_row_l & 7)) * FP_PITCH + ks * 16 + b_col_l) * 2; \
                ldsm_x2(bfv[8][0], bfv[8][1], addr);                           \
            }                                                                  \
            _Pragma("unroll")                                                  \
            for (int j = 0; j < 9; ++j)                                        \
                mma_f16(o[j], af, bfv[j]);                                     \
        }                                                                      \
        __syncwarp();                                                          \
    }

__global__ __launch_bounds__(256, 2) void flash_kernel(float* __restrict__ out, int bh0)
{
    extern __shared__ __half smh[];
    const uint32_t sbase = smem_u32(smh);

    const int tid  = threadIdx.x;
    const int lane = tid & 31;
    const int wid  = tid >> 5;
    const int g    = lane >> 2;
    const int t    = lane & 3;

    const int qt = blockIdx.x;
    const int bh = bh0 + blockIdx.y;
    const int b  = bh / H;
    const int h  = bh - b * H;
    const int qbase = qt * 128;
    const int wrow  = wid * 16;

    const int a_row_l = (lane & 7) + ((lane >> 3) & 1) * 8;
    const int a_col_l = ((lane >> 4) & 1) * 8;
    const int b_row_l = (lane & 7) + ((lane >> 4) & 1) * 8;
    const int b_col_l = ((lane >> 3) & 1) * 8;

    const __half* Qg = g_qh + (size_t)bh * S * HD;
    const __half* Kg = g_kh + (size_t)bh * S * HD;
    const __half* Vt = g_vt + (size_t)bh * HD * VT_PITCH;

#pragma unroll
    for (int kt = 0; kt < 2; ++kt) {
        const int kb = kt * 128;
        const uint32_t smK = sbase + kt * K_HALVES * 2;
        const uint32_t smV = sbase + (FV_BASE + kt * V_HALVES) * 2;
#pragma unroll
        for (int it = 0; it < 4; ++it) {
            const int f = tid + it * 256;
            const int row = f >> 3, cg = f & 7;
            const int kk = kb + row;
            const bool p = kk < S;
            cp16(smK + (row * FK_PITCH + cg * 8) * 2,
                 Kg + (size_t)(p ? kk : 0) * HD + cg * 8, p);
        }
#pragma unroll
        for (int it = 0; it < 4; ++it) {
            const int f = tid + it * 256;
            const int row = f >> 4, cg = f & 15;
            cp16(smV + (row * FP_PITCH + cg * 8) * 2,
                 Vt + (size_t)row * VT_PITCH + kb + cg * 8, true);
        }
        CP_COMMIT();
    }

    {
        const __half one  = __float2half(1.f);
        const __half zero = __float2half(0.f);
        for (int i = tid; i < 2 * 8 * FP_PITCH; i += 256) {
            const int buf = i / (8 * FP_PITCH);
            const int rem = i - buf * 8 * FP_PITCH;
            const int r   = rem / FP_PITCH;
            const int cc  = rem - r * FP_PITCH;
            smh[FV_BASE + buf * V_HALVES + (64 + r) * FP_PITCH + cc] = (r == 0) ? one : zero;
        }
    }

    {
        __half* sQ = smh + FP_BASE;
#pragma unroll
        for (int it = 0; it < 4; ++it) {
            const int f = tid + it * 256;
            const int row = f >> 3, cg = f & 7;
            const int m = qbase + row;
            uint4 u = make_uint4(0u, 0u, 0u, 0u);
            if (m < S) u = *(const uint4*)(Qg + (size_t)m * HD + cg * 8);
            *(uint4*)(sQ + row * FK_PITCH + cg * 8) = u;
        }
    }
    __syncthreads();

    uint32_t qf[4][4];
    {
        const uint32_t sQ = sbase + FP_BASE * 2;
#pragma unroll
        for (int ks = 0; ks < 4; ++ks) {
            const uint32_t addr = sQ + ((wrow + a_row_l) * FK_PITCH + ks * 16 + a_col_l) * 2;
            ldsm_x4(qf[ks][0], qf[ks][1], qf[ks][2], qf[ks][3], addr);
        }
    }
    __syncthreads();

    const int qr0 = qbase + wrow + g;
    const int qr1 = qr0 + 8;
    const __half* brow0 = g_bias + ((size_t)h * S + min(qr0, S - 1)) * BP;
    const __half* brow1 = g_bias + ((size_t)h * S + min(qr1, S - 1)) * BP;

    float m0r = -1e30f, m1r = -1e30f;
    float o[9][4];
#pragma unroll
    for (int j = 0; j < 9; ++j)
#pragma unroll
        for (int e = 0; e < 4; ++e) o[j][e] = 0.f;

    FLASH_TILE(0, 16, 8, 8)
    FLASH_TILE(1, 10, 5, 5)

    const float l0 = __shfl_sync(0xffffffffu, o[8][0], lane & ~3);
    const float l1 = __shfl_sync(0xffffffffu, o[8][2], lane & ~3);
    const float inv0 = 1.f / l0;
    const float inv1 = 1.f / l1;
#pragma unroll
    for (int j = 0; j < 8; ++j) {
        const int col = h * HD + j * 8 + 2 * t;
        if (qr0 < S) {
            float2 v; v.x = o[j][0] * inv0; v.y = o[j][1] * inv0;
            *(float2*)(out + ((size_t)b * S + qr0) * D + col) = v;
        }
        if (qr1 < S) {
            float2 v; v.x = o[j][2] * inv1; v.y = o[j][3] * inv1;
            *(float2*)(out + ((size_t)b * S + qr1) * D + col) = v;
        }
    }
}

// ============================================================================
// Launch: batch-split pipeline (unchanged from R13 winner).
// ============================================================================
extern "C" void kernel_launch(void* const* d_in, const int* in_sizes, int n_in,
                              void* d_out, int out_size)
{
    const float* X  = (const float*)d_in[0];
    const float* wq = (const float*)d_in[1];
    const float* bq = (const float*)d_in[2];
    const float* wk = (const float*)d_in[3];
    const float* wv = (const float*)d_in[4];
    const float* bv = (const float*)d_in[5];
    const float* bt = (const float*)d_in[6];
    const int*   ri = (const int*)d_in[7];
    float* out = (float*)d_out;

    (void)in_sizes; (void)n_in; (void)out_size;

    static __half* xh_ptr = nullptr;
    static __half* wh_ptr = nullptr;
    static cudaStream_t s1 = nullptr;
    static cudaEvent_t ev_fork, ev_prep, ev_xb, ev_a, ev_f;
    if (!xh_ptr) {
        cudaGetSymbolAddress((void**)&xh_ptr, g_xh);
        cudaGetSymbolAddress((void**)&wh_ptr, g_wh);
        cudaFuncSetAttribute(qkv_mma_kernel, cudaFuncAttributeMaxDynamicSharedMemorySize, SMEM_QKV_BYTES);
        cudaFuncSetAttribute(flash_kernel, cudaFuncAttributeMaxDynamicSharedMemorySize, SMEM_FLASH_BYTES);
        cudaStreamCreateWithFlags(&s1, cudaStreamNonBlocking);
        cudaEventCreateWithFlags(&ev_fork, cudaEventDisableTiming);
        cudaEventCreateWithFlags(&ev_prep, cudaEventDisableTiming);
        cudaEventCreateWithFlags(&ev_xb,   cudaEventDisableTiming);
        cudaEventCreateWithFlags(&ev_a,    cudaEventDisableTiming);
        cudaEventCreateWithFlags(&ev_f,    cudaEventDisableTiming);
    }

    const int nx8a = ROWS_A * D / 8;
    const int nx8b = (M_TOT - ROWS_A) * D / 8;
    const int nw8  = 3 * D * D / 8;

    cudaEventRecord(ev_fork, 0);
    cudaStreamWaitEvent(s1, ev_fork, 0);

    cvt_x_kernel<<<(nx8a + 255) / 256, 256>>>(X, xh_ptr, nx8a);

    cvt_w_kernel<<<(nw8 + 255) / 256, 256, 0, s1>>>(wq, wk, wv, wh_ptr);
    vt_pad_kernel<<<(B * H * HD * 16 + 255) / 256, 256, 0, s1>>>();
    bias_expand_kernel<<<(S * S + 255) / 256, 256, 0, s1>>>(bt, ri);
    cudaEventRecord(ev_prep, s1);
    cvt_x_kernel<<<(nx8b + 255) / 256, 256, 0, s1>>>(
        X + (size_t)ROWS_A * D, xh_ptr + (size_t)ROWS_A * D, nx8b);
    cudaEventRecord(ev_xb, s1);

    cudaStreamWaitEvent(0, ev_prep, 0);
    qkv_mma_kernel<<<dim3(MBLK_A, 18), 256, SMEM_QKV_BYTES>>>(bq, bv, 0);
    cudaEventRecord(ev_a, 0);

    cudaStreamWaitEvent(0, ev_xb, 0);
    qkv_mma_kernel<<<dim3(MBLK_B, 18), 256, SMEM_QKV_BYTES>>>(bq, bv, MBLK_A);

    cudaStreamWaitEvent(s1, ev_a, 0);
    flash_kernel<<<dim3(2, 32 * H), 256, SMEM_FLASH_BYTES, s1>>>(out, 0);
    cudaEventRecord(ev_f, s1);

    flash_kernel<<<dim3(2, 32 * H), 256, SMEM_FLASH_BYTES>>>(out, 32 * H);

    cudaStreamWaitEvent(0, ev_f, 0);
}

// round 16
// speedup vs baseline: 2.0094x; 1.0003x over previous
#include <cuda_runtime.h>
#include <cuda_fp16.h>
#include <math.h>
#include <cstdint>

#define B 64
#define S 197
#define D 768
#define H 12
#define HD 64
#define M_TOT (B * S)          // 12608
#define NUM_REL 732
#define VT_PITCH 256
#define BP 198
#define LOG2E 1.44269504f

#define MBLK_A 50
#define MBLK_B 49
#define ROWS_A 6400

// -------- device scratch --------
__device__ __half g_xh[(size_t)M_TOT * D];
__device__ __half g_wh[(size_t)3 * D * D];
__device__ __half g_qh[(size_t)B * H * S * HD];
__device__ __half g_kh[(size_t)B * H * S * HD];
__device__ __half g_vt[(size_t)B * H * HD * VT_PITCH];
__device__ __half g_bias[(size_t)H * S * BP];

__device__ __forceinline__ void mma_f16(float* d, const uint32_t* a, const uint32_t* b) {
    asm volatile(
        "mma.sync.aligned.m16n8k16.row.col.f32.f16.f16.f32 "
        "{%0,%1,%2,%3}, {%4,%5,%6,%7}, {%8,%9}, {%0,%1,%2,%3};"
        : "+f"(d[0]), "+f"(d[1]), "+f"(d[2]), "+f"(d[3])
        : "r"(a[0]), "r"(a[1]), "r"(a[2]), "r"(a[3]), "r"(b[0]), "r"(b[1]));
}

__device__ __forceinline__ void ldsm_x4(uint32_t& r0, uint32_t& r1, uint32_t& r2, uint32_t& r3,
                                        uint32_t addr) {
    asm volatile("ldmatrix.sync.aligned.m8n8.x4.shared.b16 {%0,%1,%2,%3}, [%4];"
                 : "=r"(r0), "=r"(r1), "=r"(r2), "=r"(r3) : "r"(addr));
}
__device__ __forceinline__ void ldsm_x2(uint32_t& r0, uint32_t& r1, uint32_t addr) {
    asm volatile("ldmatrix.sync.aligned.m8n8.x2.shared.b16 {%0,%1}, [%2];"
                 : "=r"(r0), "=r"(r1) : "r"(addr));
}

__device__ __forceinline__ uint32_t smem_u32(const void* p) {
    uint32_t a;
    asm("{ .reg .u64 t; cvta.to.shared.u64 t, %1; cvt.u32.u64 %0, t; }" : "=r"(a) : "l"(p));
    return a;
}

__device__ __forceinline__ void cp16(uint32_t dst, const void* src, bool pred) {
    const int sz = pred ? 16 : 0;
    asm volatile("cp.async.cg.shared.global [%0], [%1], 16, %2;"
                 :: "r"(dst), "l"(src), "r"(sz) : "memory");
}
#define CP_COMMIT() asm volatile("cp.async.commit_group;" ::: "memory")
#define CP_WAIT1()  asm volatile("cp.async.wait_group 1;" ::: "memory")
#define CP_WAIT0()  asm volatile("cp.async.wait_group 0;" ::: "memory")

__device__ __forceinline__ uint32_t ex2_f16x2(__half2 x) {
    uint32_t r;
    asm("ex2.approx.f16x2 %0, %1;" : "=r"(r) : "r"(*(uint32_t*)&x));
    return r;
}

// ============================================================================
// Kernel 0a: fp32 -> fp16 convert.
// ============================================================================
__global__ __launch_bounds__(256) void cvt_x_kernel(
    const float* __restrict__ src, __half* __restrict__ dst, int n8)
{
    const int i = blockIdx.x * 256 + threadIdx.x;
    if (i >= n8) return;
    const float4 a = ((const float4*)src)[2 * i];
    const float4 b = ((const float4*)src)[2 * i + 1];
    __half2 h0 = __floats2half2_rn(a.x, a.y);
    __half2 h1 = __floats2half2_rn(a.z, a.w);
    __half2 h2 = __floats2half2_rn(b.x, b.y);
    __half2 h3 = __floats2half2_rn(b.z, b.w);
    uint4 u;
    u.x = *(uint32_t*)&h0; u.y = *(uint32_t*)&h1;
    u.z = *(uint32_t*)&h2; u.w = *(uint32_t*)&h3;
    ((uint4*)dst)[i] = u;
}

// ============================================================================
// Kernel 0b: fused weight convert.
// ============================================================================
__global__ __launch_bounds__(256) void cvt_w_kernel(
    const float* __restrict__ wq, const float* __restrict__ wk,
    const float* __restrict__ wv, __half* __restrict__ dst)
{
    const int nw8 = D * D / 8;
    const int i = blockIdx.x * 256 + threadIdx.x;
    if (i >= 3 * nw8) return;
    const float* src;
    int j;
    if (i < nw8)          { src = wq; j = i; }
    else if (i < 2 * nw8) { src = wk; j = i - nw8; }
    else                  { src = wv; j = i - 2 * nw8; }
    const float4 a = ((const float4*)src)[2 * j];
    const float4 b = ((const float4*)src)[2 * j + 1];
    __half2 h0 = __floats2half2_rn(a.x, a.y);
    __half2 h1 = __floats2half2_rn(a.z, a.w);
    __half2 h2 = __floats2half2_rn(b.x, b.y);
    __half2 h3 = __floats2half2_rn(b.z, b.w);
    uint4 u;
    u.x = *(uint32_t*)&h0; u.y = *(uint32_t*)&h1;
    u.z = *(uint32_t*)&h2; u.w = *(uint32_t*)&h3;
    ((uint4*)dst)[i] = u;
}

// ============================================================================
// Kernel 0c: zero g_vt tail (k in [192,256)). Runs BEFORE qkv.
// ============================================================================
__global__ __launch_bounds__(256) void vt_pad_kernel()
{
    const int i = blockIdx.x * 256 + threadIdx.x;
    if (i >= B * H * HD * 16) return;
    const int row = i >> 4, j = i & 15;
    ((uint2*)(g_vt + (size_t)row * VT_PITCH + 192))[j] = make_uint2(0u, 0u);
}

// ============================================================================
// Kernel 1: QKV projection (R13 core; V-epilogue now smem-transposed for
// coalesced g_vt stores — the old path wrote 2B at 512B stride, 2/32 sectors).
// ============================================================================
#define HPITCH 72
#define A_HALVES (128 * HPITCH)
#define BQ_HALVES (128 * HPITCH)
#define STAGE_HALVES (A_HALVES + BQ_HALVES)
#define STAGE_BYTES (STAGE_HALVES * 2)          // 36864
#define SMEM_QKV_BYTES (3 * STAGE_BYTES)        // 110592
#define NCHUNK 12

__global__ __launch_bounds__(256, 2) void qkv_mma_kernel(
    const float* __restrict__ bq, const float* __restrict__ bv, int mblk0)
{
    extern __shared__ __half smh[];
    const uint32_t sbase = smem_u32(smh);

    const int tid  = threadIdx.x;
    const int lane = tid & 31;
    const int wid  = tid >> 5;
    const int g    = lane >> 2;
    const int t    = lane & 3;
    const int wm   = wid & 1;
    const int wn   = wid >> 1;

    const int m0  = (mblk0 + blockIdx.x) * 128;
    const int n0g = blockIdx.y * 128;
    const int proj = n0g / 768;
    const int n0   = n0g - proj * 768;

    const float* bias = (proj == 0) ? bq : ((proj == 2) ? bv : nullptr);

    const int lrow = tid >> 3;
    const int lcg  = tid & 7;

    auto issue = [&](int c, int s) {
        const int k0 = c * 64;
        const uint32_t smA = sbase + s * STAGE_BYTES;
        const uint32_t smB = smA + A_HALVES * 2;
#pragma unroll
        for (int i = 0; i < 4; ++i) {
            const int row = lrow + i * 32;
            const int m = m0 + row;
            const bool pa = m < M_TOT;
            const __half* srcA = g_xh + (size_t)(pa ? m : 0) * 768 + k0 + lcg * 8;
            cp16(smA + (row * HPITCH + lcg * 8) * 2, srcA, pa);
        }
#pragma unroll
        for (int i = 0; i < 4; ++i) {
            const int row = lrow + i * 32;
            const __half* srcB = g_wh + (size_t)(n0g + row) * 768 + k0 + lcg * 8;
            cp16(smB + (row * HPITCH + lcg * 8) * 2, srcB, true);
        }
        CP_COMMIT();
    };

    issue(0, 0);
    issue(1, 1);

    const int a_row_l = (lane & 7) + ((lane >> 3) & 1) * 8;
    const int a_col_l = ((lane >> 4) & 1) * 8;
    const int b_row_l = (lane & 7) + ((lane >> 4) & 1) * 8;
    const int b_col_l = ((lane >> 3) & 1) * 8;

    float acc[4][4][4];
#pragma unroll
    for (int mt = 0; mt < 4; ++mt)
#pragma unroll
        for (int nt = 0; nt < 4; ++nt)
#pragma unroll
            for (int e = 0; e < 4; ++e) acc[mt][nt][e] = 0.f;

    for (int c = 0; c < NCHUNK; ++c) {
        CP_WAIT1();
        __syncthreads();
        if (c + 2 < NCHUNK) issue(c + 2, (c + 2) % 3);

        const uint32_t stA = sbase + (c % 3) * STAGE_BYTES;
        const uint32_t stB = stA + A_HALVES * 2;
#pragma unroll
        for (int ks = 0; ks < 4; ++ks) {
            uint32_t af[4][4], bf[4][2];
#pragma unroll
            for (int mt = 0; mt < 4; ++mt) {
                const uint32_t addr = stA +
                    ((wm * 64 + mt * 16 + a_row_l) * HPITCH + ks * 16 + a_col_l) * 2;
                ldsm_x4(af[mt][0], af[mt][1], af[mt][2], af[mt][3], addr);
            }
#pragma unroll
            for (int ntp = 0; ntp < 2; ++ntp) {
                const uint32_t addr = stB +
                    ((wn * 32 + ntp * 16 + b_row_l) * HPITCH + ks * 16 + b_col_l) * 2;
                ldsm_x4(bf[2 * ntp][0], bf[2 * ntp][1],
                        bf[2 * ntp + 1][0], bf[2 * ntp + 1][1], addr);
            }
#pragma unroll
            for (int mt = 0; mt < 4; ++mt)
#pragma unroll
                for (int nt = 0; nt < 4; ++nt)
                    mma_f16(acc[mt][nt], af[mt], bf[nt]);
        }
    }

    if (proj != 2) {
        // ---- Q/K epilogue: direct __half2 stores (proven) ----
        const float scale = (proj == 0) ? 0.125f : 1.0f;
#pragma unroll
        for (int mt = 0; mt < 4; ++mt) {
            const int r0 = m0 + wm * 64 + mt * 16 + g;
#pragma unroll
            for (int nt = 0; nt < 4; ++nt) {
                const int n = n0 + wn * 32 + nt * 8 + t * 2;
                const int hh = n >> 6;
                const int hd = n & 63;
                float bx = 0.f, by = 0.f;
                if (bias) { bx = bias[n]; by = bias[n + 1]; }
#pragma unroll
                for (int half_i = 0; half_i < 2; ++half_i) {
                    const int m = r0 + half_i * 8;
                    if (m >= M_TOT) continue;
                    const int bb = m / S;
                    const int ss = m - bb * S;
                    const int bh = bb * H + hh;
                    __half2 hv = __floats2half2_rn(
                        (acc[mt][nt][half_i * 2 + 0] + bx) * scale,
                        (acc[mt][nt][half_i * 2 + 1] + by) * scale);
                    __half* dst = (proj == 0) ? g_qh : g_kh;
                    *(__half2*)(dst + ((size_t)bh * S + ss) * HD + hd) = hv;
                }
            }
        }
    } else {
        // ---- V epilogue: smem transpose -> coalesced g_vt stores ----
        __syncthreads();                       // stage smem now dead; reuse
        __half* tp = smh;                      // [128 n][128 m], 32 KB
#pragma unroll
        for (int mt = 0; mt < 4; ++mt) {
#pragma unroll
            for (int nt = 0; nt < 4; ++nt) {
                const int nl = wn * 32 + nt * 8 + t * 2;
                const int n  = n0 + nl;
                const float bx = bias[n];
                const float by = bias[n + 1];
#pragma unroll
                for (int half_i = 0; half_i < 2; ++half_i) {
                    const int ml = wm * 64 + mt * 16 + g + half_i * 8;
                    tp[nl * 128 + ml] =
                        __float2half_rn(acc[mt][nt][half_i * 2 + 0] + bx);
                    tp[(nl + 1) * 128 + ml] =
                        __float2half_rn(acc[mt][nt][half_i * 2 + 1] + by);
                }
            }
        }
        __syncthreads();
#pragma unroll
        for (int it = 0; it < 64; ++it) {      // 128*128 / 256
            const int idx = tid + it * 256;
            const int r  = idx >> 7;           // n_local row
            const int mm = idx & 127;          // m_local (consecutive per tid)
            const int m = m0 + mm;
            if (m >= M_TOT) continue;
            const int bb = m / S;
            const int ss = m - bb * S;
            const int n  = n0 + r;
            const int hh = n >> 6;
            const int hd = n & 63;
            g_vt[(((size_t)(bb * H + hh)) * HD + hd) * VT_PITCH + ss] = tp[r * 128 + mm];
        }
    }
}

// ============================================================================
// Kernel 2: bias expand (fp16, pitch 198).
// ============================================================================
__global__ __launch_bounds__(256) void bias_expand_kernel(
    const float* __restrict__ bias_table, const int* __restrict__ rel_index)
{
    const int i = blockIdx.x * 256 + threadIdx.x;
    if (i >= S * S) return;
    const int q = i / S, k = i - q * S;
    const int r = rel_index[i];
#pragma unroll
    for (int h = 0; h < H; ++h)
        g_bias[((size_t)h * S + q) * BP + k] = __float2half_rn(bias_table[r * H + h]);
}

// ============================================================================
// Kernel 3: flash attention (unchanged from R15 winner; literal-bound macro).
// ============================================================================
#define FK_PITCH 72
#define FP_PITCH 136
#define K_HALVES (128 * FK_PITCH)
#define V_HALVES (72 * FP_PITCH)
#define FV_BASE (2 * K_HALVES)
#define FP_BASE (2 * K_HALVES + 2 * V_HALVES)
#define SMEM_FLASH_BYTES ((FP_BASE + 128 * FP_PITCH) * 2)   // 110848

#define FLASH_TILE(KT, NJ, NJP, NPKS)                                          \
    {                                                                          \
        const int kb = (KT) * 128;                                             \
        if ((KT) == 0) { CP_WAIT1(); } else { CP_WAIT0(); }                    \
        __syncthreads();                                                       \
        const uint32_t sK = sbase + (KT) * K_HALVES * 2;                       \
        const uint32_t sV = sbase + (FV_BASE + (KT) * V_HALVES) * 2;           \
        float sacc[NJ][4];                                                     \
        _Pragma("unroll")                                                      \
        for (int j = 0; j < (NJ); ++j)                                         \
            _Pragma("unroll")                                                  \
            for (int e = 0; e < 4; ++e) sacc[j][e] = 0.f;                      \
        _Pragma("unroll")                                                      \
        for (int ks = 0; ks < 4; ++ks) {                                       \
            uint32_t bf[NJ][2];                                                \
            _Pragma("unroll")                                                  \
            for (int jp = 0; jp < (NJP); ++jp) {                               \
                const uint32_t addr = sK +                                     \
                    ((jp * 16 + b_row_l) * FK_PITCH + ks * 16 + b_col_l) * 2;  \
                ldsm_x4(bf[2 * jp][0], bf[2 * jp][1],                          \
                        bf[2 * jp + 1][0], bf[2 * jp + 1][1], addr);           \
            }                                                                  \
            _Pragma("unroll")                                                  \
            for (int j = 0; j < (NJ); ++j)                                     \
                mma_f16(sacc[j], qf[ks], bf[j]);                               \
        }                                                                      \
        _Pragma("unroll")                                                      \
        for (int j = 0; j < (NJ); ++j) {                                       \
            const int kc = kb + j * 8 + 2 * t;                                 \
            if (kc < S) {                                                      \
                const float2 b0 = __half22float2(*(const __half2*)(brow0 + kc)); \
                const float2 b1 = __half22float2(*(const __half2*)(brow1 + kc)); \
                sacc[j][0] += b0.x;                                            \
                sacc[j][1] = (kc + 1 < S) ? sacc[j][1] + b0.y : -1e30f;        \
                sacc[j][2] += b1.x;                                            \
                sacc[j][3] = (kc + 1 < S) ? sacc[j][3] + b1.y : -1e30f;        \
            } else {                                                           \
                sacc[j][0] = -1e30f; sacc[j][1] = -1e30f;                      \
                sacc[j][2] = -1e30f; sacc[j][3] = -1e30f;                      \
            }                                                                  \
        }                                                                      \
        float mx0 = -1e30f, mx1 = -1e30f;                                      \
        _Pragma("unroll")                                                      \
        for (int j = 0; j < (NJ); ++j) {                                       \
            mx0 = fmaxf(mx0, fmaxf(sacc[j][0], sacc[j][1]));                   \
            mx1 = fmaxf(mx1, fmaxf(sacc[j][2], sacc[j][3]));                   \
        }                                                                      \
        mx0 = fmaxf(mx0, __shfl_xor_sync(0xffffffffu, mx0, 1));                \
        mx0 = fmaxf(mx0, __shfl_xor_sync(0xffffffffu, mx0, 2));                \
        mx1 = fmaxf(mx1, __shfl_xor_sync(0xffffffffu, mx1, 1));                \
        mx1 = fmaxf(mx1, __shfl_xor_sync(0xffffffffu, mx1, 2));                \
        const float nm0 = fmaxf(m0r, mx0);                                     \
        const float nm1 = fmaxf(m1r, mx1);                                     \
        const float sc0 = __expf(m0r - nm0);                                   \
        const float sc1 = __expf(m1r - nm1);                                   \
        m0r = nm0; m1r = nm1;                                                  \
        const float c0 = -nm0 * LOG2E;                                         \
        const float c1 = -nm1 * LOG2E;                                         \
        __half* sPp = smh + FP_BASE;                                           \
        _Pragma("unroll")                                                      \
        for (int j = 0; j < (NJ); ++j) {                                       \
            const int col = j * 8 + 2 * t;                                     \
            __half2 a0 = __floats2half2_rn(fmaf(sacc[j][0], LOG2E, c0),        \
                                           fmaf(sacc[j][1], LOG2E, c0));       \
            __half2 a1 = __floats2half2_rn(fmaf(sacc[j][2], LOG2E, c1),        \
                                           fmaf(sacc[j][3], LOG2E, c1));       \
            *(uint32_t*)(sPp + (wrow + g) * FP_PITCH + col)     = ex2_f16x2(a0); \
            *(uint32_t*)(sPp + (wrow + g + 8) * FP_PITCH + col) = ex2_f16x2(a1); \
        }                                                                      \
        _Pragma("unroll")                                                      \
        for (int j = 0; j < 9; ++j) {                                          \
            o[j][0] *= sc0; o[j][1] *= sc0;                                    \
            o[j][2] *= sc1; o[j][3] *= sc1;                                    \
        }                                                                      \
        __syncwarp();                                                          \
        const uint32_t sP = sbase + FP_BASE * 2;                               \
        _Pragma("unroll")                                                      \
        for (int ks = 0; ks < (NPKS); ++ks) {                                  \
            uint32_t af[4];                                                    \
            {                                                                  \
                const uint32_t addr = sP +                                     \
                    ((wrow + a_row_l) * FP_PITCH + ks * 16 + a_col_l) * 2;     \
                ldsm_x4(af[0], af[1], af[2], af[3], addr);                     \
            }                                                                  \
            uint32_t bfv[9][2];                                                \
            _Pragma("unroll")                                                  \
            for (int jp = 0; jp < 4; ++jp) {                                   \
                const uint32_t addr = sV +                                     \
                    ((jp * 16 + b_row_l) * FP_PITCH + ks * 16 + b_col_l) * 2;  \
                ldsm_x4(bfv[2 * jp][0], bfv[2 * jp][1],                        \
                        bfv[2 * jp + 1][0], bfv[2 * jp + 1][1], addr);         \
            }                                                                  \
            {                                                                  \
                const uint32_t addr = sV +                                     \
                    ((64 + (b_row_l & 7)) * FP_PITCH + ks * 16 + b_col_l) * 2; \
                ldsm_x2(bfv[8][0], bfv[8][1], addr);                           \
            }                                                                  \
            _Pragma("unroll")                                                  \
            for (int j = 0; j < 9; ++j)                                        \
                mma_f16(o[j], af, bfv[j]);                                     \
        }                                                                      \
        __syncwarp();                                                          \
    }

__global__ __launch_bounds__(256, 2) void flash_kernel(float* __restrict__ out, int bh0)
{
    extern __shared__ __half smh[];
    const uint32_t sbase = smem_u32(smh);

    const int tid  = threadIdx.x;
    const int lane = tid & 31;
    const int wid  = tid >> 5;
    const int g    = lane >> 2;
    const int t    = lane & 3;

    const int qt = blockIdx.x;
    const int bh = bh0 + blockIdx.y;
    const int b  = bh / H;
    const int h  = bh - b * H;
    const int qbase = qt * 128;
    const int wrow  = wid * 16;

    const int a_row_l = (lane & 7) + ((lane >> 3) & 1) * 8;
    const int a_col_l = ((lane >> 4) & 1) * 8;
    const int b_row_l = (lane & 7) + ((lane >> 4) & 1) * 8;
    const int b_col_l = ((lane >> 3) & 1) * 8;

    const __half* Qg = g_qh + (size_t)bh * S * HD;
    const __half* Kg = g_kh + (size_t)bh * S * HD;
    const __half* Vt = g_vt + (size_t)bh * HD * VT_PITCH;

#pragma unroll
    for (int kt = 0; kt < 2; ++kt) {
        const int kb = kt * 128;
        const uint32_t smK = sbase + kt * K_HALVES * 2;
        const uint32_t smV = sbase + (FV_BASE + kt * V_HALVES) * 2;
#pragma unroll
        for (int it = 0; it < 4; ++it) {
            const int f = tid + it * 256;
            const int row = f >> 3, cg = f & 7;
            const int kk = kb + row;
            const bool p = kk < S;
            cp16(smK + (row * FK_PITCH + cg * 8) * 2,
                 Kg + (size_t)(p ? kk : 0) * HD + cg * 8, p);
        }
#pragma unroll
        for (int it = 0; it < 4; ++it) {
            const int f = tid + it * 256;
            const int row = f >> 4, cg = f & 15;
            cp16(smV + (row * FP_PITCH + cg * 8) * 2,
                 Vt + (size_t)row * VT_PITCH + kb + cg * 8, true);
        }
        CP_COMMIT();
    }

    {
        const __half one  = __float2half(1.f);
        const __half zero = __float2half(0.f);
        for (int i = tid; i < 2 * 8 * FP_PITCH; i += 256) {
            const int buf = i / (8 * FP_PITCH);
            const int rem = i - buf * 8 * FP_PITCH;
            const int r   = rem / FP_PITCH;
            const int cc  = rem - r * FP_PITCH;
            smh[FV_BASE + buf * V_HALVES + (64 + r) * FP_PITCH + cc] = (r == 0) ? one : zero;
        }
    }

    {
        __half* sQ = smh + FP_BASE;
#pragma unroll
        for (int it = 0; it < 4; ++it) {
            const int f = tid + it * 256;
            const int row = f >> 3, cg = f & 7;
            const int m = qbase + row;
            uint4 u = make_uint4(0u, 0u, 0u, 0u);
            if (m < S) u = *(const uint4*)(Qg + (size_t)m * HD + cg * 8);
            *(uint4*)(sQ + row * FK_PITCH + cg * 8) = u;
        }
    }
    __syncthreads();

    uint32_t qf[4][4];
    {
        const uint32_t sQ = sbase + FP_BASE * 2;
#pragma unroll
        for (int ks = 0; ks < 4; ++ks) {
            const uint32_t addr = sQ + ((wrow + a_row_l) * FK_PITCH + ks * 16 + a_col_l) * 2;
            ldsm_x4(qf[ks][0], qf[ks][1], qf[ks][2], qf[ks][3], addr);
        }
    }
    __syncthreads();

    const int qr0 = qbase + wrow + g;
    const int qr1 = qr0 + 8;
    const __half* brow0 = g_bias + ((size_t)h * S + min(qr0, S - 1)) * BP;
    const __half* brow1 = g_bias + ((size_t)h * S + min(qr1, S - 1)) * BP;

    float m0r = -1e30f, m1r = -1e30f;
    float o[9][4];
#pragma unroll
    for (int j = 0; j < 9; ++j)
#pragma unroll
        for (int e = 0; e < 4; ++e) o[j][e] = 0.f;

    FLASH_TILE(0, 16, 8, 8)
    FLASH_TILE(1, 10, 5, 5)

    const float l0 = __shfl_sync(0xffffffffu, o[8][0], lane & ~3);
    const float l1 = __shfl_sync(0xffffffffu, o[8][2], lane & ~3);
    const float inv0 = 1.f / l0;
    const float inv1 = 1.f / l1;
#pragma unroll
    for (int j = 0; j < 8; ++j) {
        const int col = h * HD + j * 8 + 2 * t;
        if (qr0 < S) {
            float2 v; v.x = o[j][0] * inv0; v.y = o[j][1] * inv0;
            *(float2*)(out + ((size_t)b * S + qr0) * D + col) = v;
        }
        if (qr1 < S) {
            float2 v; v.x = o[j][2] * inv1; v.y = o[j][3] * inv1;
            *(float2*)(out + ((size_t)b * S + qr1) * D + col) = v;
        }
    }
}

// ============================================================================
// Launch: batch-split pipeline (unchanged from R13/R15 winner).
// ============================================================================
extern "C" void kernel_launch(void* const* d_in, const int* in_sizes, int n_in,
                              void* d_out, int out_size)
{
    const float* X  = (const float*)d_in[0];
    const float* wq = (const float*)d_in[1];
    const float* bq = (const float*)d_in[2];
    const float* wk = (const float*)d_in[3];
    const float* wv = (const float*)d_in[4];
    const float* bv = (const float*)d_in[5];
    const float* bt = (const float*)d_in[6];
    const int*   ri = (const int*)d_in[7];
    float* out = (float*)d_out;

    (void)in_sizes; (void)n_in; (void)out_size;

    static __half* xh_ptr = nullptr;
    static __half* wh_ptr = nullptr;
    static cudaStream_t s1 = nullptr;
    static cudaEvent_t ev_fork, ev_prep, ev_xb, ev_a, ev_f;
    if (!xh_ptr) {
        cudaGetSymbolAddress((void**)&xh_ptr, g_xh);
        cudaGetSymbolAddress((void**)&wh_ptr, g_wh);
        cudaFuncSetAttribute(qkv_mma_kernel, cudaFuncAttributeMaxDynamicSharedMemorySize, SMEM_QKV_BYTES);
        cudaFuncSetAttribute(flash_kernel, cudaFuncAttributeMaxDynamicSharedMemorySize, SMEM_FLASH_BYTES);
        cudaStreamCreateWithFlags(&s1, cudaStreamNonBlocking);
        cudaEventCreateWithFlags(&ev_fork, cudaEventDisableTiming);
        cudaEventCreateWithFlags(&ev_prep, cudaEventDisableTiming);
        cudaEventCreateWithFlags(&ev_xb,   cudaEventDisableTiming);
        cudaEventCreateWithFlags(&ev_a,    cudaEventDisableTiming);
        cudaEventCreateWithFlags(&ev_f,    cudaEventDisableTiming);
    }

    const int nx8a = ROWS_A * D / 8;
    const int nx8b = (M_TOT - ROWS_A) * D / 8;
    const int nw8  = 3 * D * D / 8;

    cudaEventRecord(ev_fork, 0);
    cudaStreamWaitEvent(s1, ev_fork, 0);

    cvt_x_kernel<<<(nx8a + 255) / 256, 256>>>(X, xh_ptr, nx8a);

    cvt_w_kernel<<<(nw8 + 255) / 256, 256, 0, s1>>>(wq, wk, wv, wh_ptr);
    vt_pad_kernel<<<(B * H * HD * 16 + 255) / 256, 256, 0, s1>>>();
    bias_expand_kernel<<<(S * S + 255) / 256, 256, 0, s1>>>(bt, ri);
    cudaEventRecord(ev_prep, s1);
    cvt_x_kernel<<<(nx8b + 255) / 256, 256, 0, s1>>>(
        X + (size_t)ROWS_A * D, xh_ptr + (size_t)ROWS_A * D, nx8b);
    cudaEventRecord(ev_xb, s1);

    cudaStreamWaitEvent(0, ev_prep, 0);
    qkv_mma_kernel<<<dim3(MBLK_A, 18), 256, SMEM_QKV_BYTES>>>(bq, bv, 0);
    cudaEventRecord(ev_a, 0);

    cudaStreamWaitEvent(0, ev_xb, 0);
    qkv_mma_kernel<<<dim3(MBLK_B, 18), 256, SMEM_QKV_BYTES>>>(bq, bv, MBLK_A);

    cudaStreamWaitEvent(s1, ev_a, 0);
    flash_kernel<<<dim3(2, 32 * H), 256, SMEM_FLASH_BYTES, s1>>>(out, 0);
    cudaEventRecord(ev_f, s1);

    flash_kernel<<<dim3(2, 32 * H), 256, SMEM_FLASH_BYTES>>>(out, 32 * H);

    cudaStreamWaitEvent(0, ev_f, 0);
}